// round 16
// baseline (speedup 1.0000x reference)
#include <cuda_runtime.h>
#include <cuda_fp16.h>
#include <cstdint>
#include <math.h>

#define NTOK 4096
#define EMB  1024
#define HID  2816
#define NE   8
#define MAXPAD 9216

// ===================== device scratch =====================
__device__ int   g_cnt[NE];
__device__ int   g_tok[NE][NTOK];
__device__ float g_gate[NE][NTOK];

__device__ __half g_xp[(size_t)MAXPAD * EMB];
__device__ __half g_h [(size_t)MAXPAD * HID];
__device__ __half g_w1h[(size_t)NE * HID * EMB];   // [e][n][k]
__device__ __half g_w3h[(size_t)NE * HID * EMB];
__device__ __half g_w2h[(size_t)NE * EMB * HID];   // [e][n=EMB][k=HID]

// ===================== helpers =====================
__device__ __forceinline__ void mma16(float* c, const uint32_t* a, const uint32_t* b) {
    asm volatile("mma.sync.aligned.m16n8k16.row.col.f32.f16.f16.f32 "
        "{%0,%1,%2,%3}, {%4,%5,%6,%7}, {%8,%9}, {%0,%1,%2,%3};"
        : "+f"(c[0]), "+f"(c[1]), "+f"(c[2]), "+f"(c[3])
        : "r"(a[0]), "r"(a[1]), "r"(a[2]), "r"(a[3]), "r"(b[0]), "r"(b[1]));
}
__device__ __forceinline__ void ldsm4(uint32_t* r, uint32_t addr) {
    asm volatile("ldmatrix.sync.aligned.m8n8.x4.shared.b16 {%0,%1,%2,%3}, [%4];"
        : "=r"(r[0]), "=r"(r[1]), "=r"(r[2]), "=r"(r[3]) : "r"(addr));
}
__device__ __forceinline__ uint32_t s2u(const void* p) {
    uint32_t a;
    asm("{ .reg .u64 t; cvta.to.shared.u64 t, %1; cvt.u32.u64 %0, t; }" : "=r"(a) : "l"(p));
    return a;
}
__device__ __forceinline__ void cp16(uint32_t dst, const void* src) {
    asm volatile("cp.async.cg.shared.global [%0], [%1], 16;" :: "r"(dst), "l"(src));
}
#define CP_COMMIT() asm volatile("cp.async.commit_group;" ::: "memory")

__device__ __forceinline__ int offp_of(int e) {
    int o = 0;
    for (int i = 0; i < NE; i++) if (i < e) o += (g_cnt[i] + 127) & ~127;
    return o;
}

// ===== fused: fp16-convert + transpose weights to [e][n][k], reset cnt =====
__global__ void k_roundT(const float* __restrict__ w1,
                         const float* __restrict__ w3,
                         const float* __restrict__ w2) {
    __shared__ float t[32][33];
    int which = blockIdx.z / NE, e = blockIdx.z % NE;
    if (which == 0 && blockIdx.x == 0 && blockIdx.y == 0 &&
        threadIdx.y == 0 && threadIdx.x < NE) g_cnt[threadIdx.x] = 0;

    const float* in; __half* outp; int K, N, nt, kt;
    if (which < 2) {
        in = ((which == 0) ? w1 : w3) + (size_t)e * EMB * HID;
        outp = ((which == 0) ? g_w1h : g_w3h) + (size_t)e * HID * EMB;
        K = EMB; N = HID; nt = blockIdx.x; kt = blockIdx.y;
    } else {
        in = w2 + (size_t)e * HID * EMB;
        outp = g_w2h + (size_t)e * EMB * HID;
        K = HID; N = EMB; kt = blockIdx.x; nt = blockIdx.y;
    }
    int tx = threadIdx.x, ty = threadIdx.y;
#pragma unroll
    for (int i = 0; i < 4; i++)
        t[ty + 8 * i][tx] = in[(size_t)(kt * 32 + ty + 8 * i) * N + nt * 32 + tx];
    __syncthreads();
#pragma unroll
    for (int i = 0; i < 4; i++)
        outp[(size_t)(nt * 32 + ty + 8 * i) * K + kt * 32 + tx] =
            __float2half_rn(t[tx][ty + 8 * i]);
}

// ===================== router =====================
__global__ void k_router(const float* __restrict__ x, const float* __restrict__ wr) {
    int t    = blockIdx.x * (blockDim.x >> 5) + (threadIdx.x >> 5);
    int lane = threadIdx.x & 31;
    if (t >= NTOK) return;
    const float* xr = x + (size_t)t * EMB;
    float acc[NE];
#pragma unroll
    for (int e = 0; e < NE; e++) acc[e] = 0.f;
    for (int i = lane; i < EMB; i += 32) {
        float xv = xr[i];
#pragma unroll
        for (int e = 0; e < NE; e++) acc[e] += xv * wr[i * NE + e];
    }
#pragma unroll
    for (int e = 0; e < NE; e++)
#pragma unroll
        for (int o = 16; o > 0; o >>= 1) acc[e] += __shfl_xor_sync(0xffffffffu, acc[e], o);
    if (lane == 0) {
        int i0 = 0; float v0 = acc[0];
#pragma unroll
        for (int e = 1; e < NE; e++) if (acc[e] > v0) { v0 = acc[e]; i0 = e; }
        int i1 = -1; float v1 = -3.4e38f;
#pragma unroll
        for (int e = 0; e < NE; e++) if (e != i0 && acc[e] > v1) { v1 = acc[e]; i1 = e; }
        float z  = expf(v1 - v0);
        float p0 = 1.f / (1.f + z);
        float p1 = z  / (1.f + z);
        int s0 = atomicAdd(&g_cnt[i0], 1);
        g_tok[i0][s0] = t; g_gate[i0][s0] = p0;
        int s1 = atomicAdd(&g_cnt[i1], 1);
        g_tok[i1][s1] = t; g_gate[i1][s1] = p1;
    }
}

// ===================== gather -> fp16 ====================
__global__ void k_gather(const float* __restrict__ x) {
    int e = blockIdx.y; int cnt = g_cnt[e];
    int m0 = blockIdx.x * 16;
    int padded = (cnt + 127) & ~127;
    if (m0 >= padded) return;
    __half* dst = g_xp + (size_t)(offp_of(e) + m0) * EMB;
    for (int idx = threadIdx.x; idx < 16 * 128; idx += 256) {
        int r = idx >> 7, j = idx & 127;
        int gm = m0 + r;
        uint4 o = make_uint4(0, 0, 0, 0);
        if (gm < cnt) {
            const float4* src = (const float4*)(x + (size_t)g_tok[e][gm] * EMB) + j * 2;
            float4 v0 = src[0], v1 = src[1];
            __half2 h0 = __floats2half2_rn(v0.x, v0.y);
            __half2 h1 = __floats2half2_rn(v0.z, v0.w);
            __half2 h2 = __floats2half2_rn(v1.x, v1.y);
            __half2 h3 = __floats2half2_rn(v1.z, v1.w);
            o = make_uint4(*(uint32_t*)&h0, *(uint32_t*)&h1,
                           *(uint32_t*)&h2, *(uint32_t*)&h3);
        }
        ((uint4*)(dst + (size_t)r * EMB))[j] = o;
    }
}

// ===================== GEMM1: H = silu(X@W1)*(X@W3) =====================
// CTA tile 128(M)x64(N)x64(K), 8 warps (4x2), warp tile 32x32, 2 CTAs/SM
#define AK    72
#define A_T_H (128 * AK)
#define B_T_H (64 * AK)
#define ST1H  (A_T_H + 2 * B_T_H)
#define STG1  3
#define KB1   (EMB / 64)            // 16

__global__ void __launch_bounds__(256, 2) k_mma1() {
    extern __shared__ __half smh[];
    int e = blockIdx.z;
    int cnt = g_cnt[e];
    int m0 = blockIdx.y * 128;
    if (m0 >= cnt) return;
    int n0 = blockIdx.x * 64;
    int tid = threadIdx.x, lane = tid & 31, wid = tid >> 5;
    int wm = wid >> 1, wn = wid & 1;
    int grp = lane >> 2, q = lane & 3;
    uint32_t sbase = s2u(smh);
    int ho = offp_of(e) + m0;

    uint32_t aoff[2], boff[2];
#pragma unroll
    for (int i = 0; i < 2; i++)
        aoff[i] = (uint32_t)(((wm * 32 + i * 16 + (lane & 15)) * AK + 8 * (lane >> 4)) * 2);
#pragma unroll
    for (int jp = 0; jp < 2; jp++)
        boff[jp] = (uint32_t)(((wn * 32 + jp * 16 + (lane & 7) + 8 * (lane >> 4)) * AK
                               + 8 * ((lane >> 3) & 1)) * 2);

    const __half* gA  = g_xp  + (size_t)ho * EMB;
    const __half* gB1 = g_w1h + ((size_t)e * HID + n0) * EMB;
    const __half* gB3 = g_w3h + ((size_t)e * HID + n0) * EMB;

    auto load_stage = [&](int kb, int s) {
        uint32_t st = sbase + (uint32_t)s * ST1H * 2;
        int k0 = kb * 64;
#pragma unroll
        for (int it = 0; it < 4; it++) {
            int id = it * 256 + tid;
            int r = id >> 3, c = id & 7;
            cp16(st + (uint32_t)(r * AK) * 2 + c * 16, gA + (size_t)r * EMB + k0 + c * 8);
        }
#pragma unroll
        for (int it = 0; it < 2; it++) {
            int id = it * 256 + tid;
            int r = id >> 3, c = id & 7;
            uint32_t so = (uint32_t)(r * AK) * 2 + c * 16;
            const size_t go = (size_t)r * EMB + k0 + c * 8;
            cp16(st + A_T_H * 2 + so,           gB1 + go);
            cp16(st + (A_T_H + B_T_H) * 2 + so, gB3 + go);
        }
        CP_COMMIT();
    };

    float accZ[2][4][4], accG[2][4][4];
#pragma unroll
    for (int i = 0; i < 2; i++)
#pragma unroll
        for (int j = 0; j < 4; j++)
#pragma unroll
            for (int r = 0; r < 4; r++) { accZ[i][j][r] = 0.f; accG[i][j][r] = 0.f; }

#pragma unroll
    for (int p = 0; p < STG1 - 1; p++) load_stage(p, p);

#pragma unroll
    for (int kb = 0; kb < KB1; kb++) {
        asm volatile("cp.async.wait_group %0;" :: "n"(STG1 - 2) : "memory");
        __syncthreads();
        uint32_t stA = sbase + (uint32_t)(kb % STG1) * ST1H * 2;
        uint32_t stB1 = stA + A_T_H * 2;
        uint32_t stB3 = stA + (A_T_H + B_T_H) * 2;
#pragma unroll
        for (int ks = 0; ks < 4; ks++) {
            uint32_t ko = ks * 32;
            uint32_t a[2][4], b1[4], b3[4];
#pragma unroll
            for (int i = 0; i < 2; i++) ldsm4(a[i], stA + aoff[i] + ko);
            ldsm4(b1, stB1 + boff[0] + ko);
            ldsm4(b3, stB3 + boff[0] + ko);
#pragma unroll
            for (int i = 0; i < 2; i++) {
                mma16(accZ[i][0], a[i], b1);
                mma16(accZ[i][1], a[i], b1 + 2);
                mma16(accG[i][0], a[i], b3);
                mma16(accG[i][1], a[i], b3 + 2);
            }
            ldsm4(b1, stB1 + boff[1] + ko);
            ldsm4(b3, stB3 + boff[1] + ko);
#pragma unroll
            for (int i = 0; i < 2; i++) {
                mma16(accZ[i][2], a[i], b1);
                mma16(accZ[i][3], a[i], b1 + 2);
                mma16(accG[i][2], a[i], b3);
                mma16(accG[i][3], a[i], b3 + 2);
            }
        }
        if (kb + STG1 - 1 < KB1) load_stage(kb + STG1 - 1, (kb + STG1 - 1) % STG1);
        else CP_COMMIT();
    }

    __half* gH = g_h + (size_t)ho * HID + n0;
#pragma unroll
    for (int i = 0; i < 2; i++) {
        int r = wm * 32 + i * 16 + grp;
#pragma unroll
        for (int j = 0; j < 4; j++) {
            int c = wn * 32 + j * 8 + 2 * q;
            float h[4];
#pragma unroll
            for (int t2 = 0; t2 < 4; t2++) {
                float z = accZ[i][j][t2];
                float g = accG[i][j][t2];
                h[t2] = (z / (1.f + __expf(-z))) * g;
            }
            __half2 lo = __floats2half2_rn(h[0], h[1]);
            __half2 hi = __floats2half2_rn(h[2], h[3]);
            *(uint32_t*)(gH + (size_t)r * HID + c)       = *(uint32_t*)&lo;
            *(uint32_t*)(gH + (size_t)(r + 8) * HID + c) = *(uint32_t*)&hi;
        }
    }
}

// ===================== GEMM2: out += gate * (H @ W2) =====================
// CTA tile 128(M)x128(N)x64(K), 8 warps (4x2), warp tile 32x64, 2 CTAs/SM
#define B2_T_H (128 * AK)               // 9216 halves
#define ST2H  (A_T_H + B2_T_H)          // 18432 halves = 36864 B
#define STG2  3
#define KB2   (HID / 64)                // 44

__global__ void __launch_bounds__(256, 2) k_mma2(float* __restrict__ out) {
    extern __shared__ __half smh[];
    int e = blockIdx.z;
    int cnt = g_cnt[e];
    int m0 = blockIdx.y * 128;
    if (m0 >= cnt) return;
    int n0 = blockIdx.x * 128;
    int tid = threadIdx.x, lane = tid & 31, wid = tid >> 5;
    int wm = wid >> 1, wn = wid & 1;      // 4 x 2: warp tile 32(M) x 64(N)
    int grp = lane >> 2, q = lane & 3;
    uint32_t sbase = s2u(smh);
    int ho = offp_of(e) + m0;

    uint32_t aoff[2], boff[4];
#pragma unroll
    for (int i = 0; i < 2; i++)
        aoff[i] = (uint32_t)(((wm * 32 + i * 16 + (lane & 15)) * AK + 8 * (lane >> 4)) * 2);
#pragma unroll
    for (int jp = 0; jp < 4; jp++)
        boff[jp] = (uint32_t)(((wn * 64 + jp * 16 + (lane & 7) + 8 * (lane >> 4)) * AK
                               + 8 * ((lane >> 3) & 1)) * 2);

    const __half* gA = g_h   + (size_t)ho * HID;
    const __half* gB = g_w2h + ((size_t)e * EMB + n0) * HID;

    auto load_stage = [&](int kb, int s) {
        uint32_t st = sbase + (uint32_t)s * ST2H * 2;
        int k0 = kb * 64;
#pragma unroll
        for (int it = 0; it < 4; it++) {
            int id = it * 256 + tid;
            int r = id >> 3, c = id & 7;
            uint32_t so = (uint32_t)(r * AK) * 2 + c * 16;
            cp16(st + so,              gA + (size_t)r * HID + k0 + c * 8);
            cp16(st + A_T_H * 2 + so,  gB + (size_t)r * HID + k0 + c * 8);
        }
        CP_COMMIT();
    };

    float acc[2][8][4];
#pragma unroll
    for (int i = 0; i < 2; i++)
#pragma unroll
        for (int j = 0; j < 8; j++)
#pragma unroll
            for (int r = 0; r < 4; r++) acc[i][j][r] = 0.f;

#pragma unroll
    for (int p = 0; p < STG2 - 1; p++) load_stage(p, p);

    for (int kb = 0; kb < KB2; kb++) {
        asm volatile("cp.async.wait_group %0;" :: "n"(STG2 - 2) : "memory");
        __syncthreads();
        uint32_t stA = sbase + (uint32_t)(kb % STG2) * ST2H * 2;
        uint32_t stB = stA + A_T_H * 2;

        // fragment-pipelined mainloop: b double-buffered across (ks,jp) steps,
        // a double-buffered across ks.
        uint32_t a[2][2][4], b[2][4];
        ldsm4(a[0][0], stA + aoff[0]);
        ldsm4(a[0][1], stA + aoff[1]);
        ldsm4(b[0], stB + boff[0]);
#pragma unroll
        for (int ks = 0; ks < 4; ks++) {
            int cks = ks & 1;
#pragma unroll
            for (int jp = 0; jp < 4; jp++) {
                int cb = (ks * 4 + jp) & 1;
                if (jp < 3) {
                    ldsm4(b[cb ^ 1], stB + boff[jp + 1] + (uint32_t)ks * 32);
                } else if (ks < 3) {
                    uint32_t ko2 = (uint32_t)(ks + 1) * 32;
                    ldsm4(a[cks ^ 1][0], stA + aoff[0] + ko2);
                    ldsm4(a[cks ^ 1][1], stA + aoff[1] + ko2);
                    ldsm4(b[cb ^ 1], stB + boff[0] + ko2);
                }
#pragma unroll
                for (int i = 0; i < 2; i++) {
                    mma16(acc[i][jp * 2],     a[cks][i], b[cb]);
                    mma16(acc[i][jp * 2 + 1], a[cks][i], b[cb] + 2);
                }
            }
        }
        if (kb + STG2 - 1 < KB2)
            load_stage(kb + STG2 - 1, (kb + STG2 - 1) % STG2);
        else CP_COMMIT();
    }

#pragma unroll
    for (int i = 0; i < 2; i++) {
        int r = wm * 32 + i * 16 + grp;
        int row0 = m0 + r, row1 = row0 + 8;
        bool act0 = row0 < cnt, act1 = row1 < cnt;
        int   t0 = act0 ? g_tok[e][row0] : 0;
        int   t1 = act1 ? g_tok[e][row1] : 0;
        float gt0 = act0 ? g_gate[e][row0] : 0.f;
        float gt1 = act1 ? g_gate[e][row1] : 0.f;
        float* o0 = out + (size_t)t0 * EMB + n0;
        float* o1 = out + (size_t)t1 * EMB + n0;
#pragma unroll
        for (int j = 0; j < 8; j++) {
            int c = wn * 64 + j * 8 + 2 * q;
            if (act0) {
                atomicAdd(&o0[c],     gt0 * acc[i][j][0]);
                atomicAdd(&o0[c + 1], gt0 * acc[i][j][1]);
            }
            if (act1) {
                atomicAdd(&o1[c],     gt1 * acc[i][j][2]);
                atomicAdd(&o1[c + 1], gt1 * acc[i][j][3]);
            }
        }
    }
}

// ===================== launcher =====================
extern "C" void kernel_launch(void* const* d_in, const int* in_sizes, int n_in,
                              void* d_out, int out_size) {
    const float* x  = (const float*)d_in[0];
    const float* wr = (const float*)d_in[1];
    const float* w1 = (const float*)d_in[2];
    const float* w3 = (const float*)d_in[3];
    const float* w2 = (const float*)d_in[4];
    float* out = (float*)d_out;

    const int SM1 = STG1 * ST1H * 2;   // 110592
    const int SM2 = STG2 * ST2H * 2;   // 110592
    cudaFuncSetAttribute(k_mma1, cudaFuncAttributeMaxDynamicSharedMemorySize, SM1);
    cudaFuncSetAttribute(k_mma2, cudaFuncAttributeMaxDynamicSharedMemorySize, SM2);

    k_roundT<<<dim3(HID / 32, EMB / 32, 3 * NE), dim3(32, 8)>>>(w1, w3, w2);
    k_router<<<NTOK / 8, 256>>>(x, wr);
    k_gather<<<dim3(NTOK / 16, NE), 256>>>(x);

    k_mma1<<<dim3(HID / 64, NTOK / 128, NE), 256, SM1>>>();

    cudaMemsetAsync(out, 0, (size_t)out_size * sizeof(float));
    k_mma2<<<dim3(EMB / 128, NTOK / 128, NE), 256, SM2>>>(out);
}

// round 17
// speedup vs baseline: 1.0362x; 1.0362x over previous
#include <cuda_runtime.h>
#include <cuda_fp16.h>
#include <cstdint>
#include <math.h>

#define NTOK 4096
#define EMB  1024
#define HID  2816
#define NE   8
#define MAXPAD 9216

// ===================== device scratch =====================
__device__ int   g_cnt[NE];
__device__ int   g_tok[NE][NTOK];
__device__ float g_gate[NE][NTOK];

__device__ __half g_xp[(size_t)MAXPAD * EMB];
__device__ __half g_h [(size_t)MAXPAD * HID];
__device__ __half g_w1h[(size_t)NE * HID * EMB];   // [e][n][k]
__device__ __half g_w3h[(size_t)NE * HID * EMB];
__device__ __half g_w2h[(size_t)NE * EMB * HID];   // [e][n=EMB][k=HID]

// ===================== helpers =====================
__device__ __forceinline__ void mma16(float* c, const uint32_t* a, const uint32_t* b) {
    asm volatile("mma.sync.aligned.m16n8k16.row.col.f32.f16.f16.f32 "
        "{%0,%1,%2,%3}, {%4,%5,%6,%7}, {%8,%9}, {%0,%1,%2,%3};"
        : "+f"(c[0]), "+f"(c[1]), "+f"(c[2]), "+f"(c[3])
        : "r"(a[0]), "r"(a[1]), "r"(a[2]), "r"(a[3]), "r"(b[0]), "r"(b[1]));
}
__device__ __forceinline__ void ldsm4(uint32_t* r, uint32_t addr) {
    asm volatile("ldmatrix.sync.aligned.m8n8.x4.shared.b16 {%0,%1,%2,%3}, [%4];"
        : "=r"(r[0]), "=r"(r[1]), "=r"(r[2]), "=r"(r[3]) : "r"(addr));
}
__device__ __forceinline__ uint32_t s2u(const void* p) {
    uint32_t a;
    asm("{ .reg .u64 t; cvta.to.shared.u64 t, %1; cvt.u32.u64 %0, t; }" : "=r"(a) : "l"(p));
    return a;
}
__device__ __forceinline__ void cp16(uint32_t dst, const void* src) {
    asm volatile("cp.async.cg.shared.global [%0], [%1], 16;" :: "r"(dst), "l"(src));
}
#define CP_COMMIT() asm volatile("cp.async.commit_group;" ::: "memory")

__device__ __forceinline__ int offp_of(int e) {
    int o = 0;
    for (int i = 0; i < NE; i++) if (i < e) o += (g_cnt[i] + 127) & ~127;
    return o;
}

// ===== fused fp16-convert + transpose, vectorized half2 stores =====
// grid (88, 16, 3*NE), block (32,8).
// which<2 (w1/w3): tile = 64 k x 32 n at (kt=by, nt=bx), K=EMB, N=HID.
// which==2 (w2):   flat = bx*16+by -> kt=flat%44, nt=flat/44, K=HID, N=EMB.
__global__ void k_roundT(const float* __restrict__ w1,
                         const float* __restrict__ w3,
                         const float* __restrict__ w2) {
    __shared__ float t[64][33];
    int which = blockIdx.z / NE, e = blockIdx.z % NE;
    if (which == 0 && blockIdx.x == 0 && blockIdx.y == 0 &&
        threadIdx.y == 0 && threadIdx.x < NE) g_cnt[threadIdx.x] = 0;

    const float* in; __half* outp; int K, N, k0, n0;
    if (which < 2) {
        in   = ((which == 0) ? w1 : w3) + (size_t)e * EMB * HID;
        outp = ((which == 0) ? g_w1h : g_w3h) + (size_t)e * HID * EMB;
        K = EMB; N = HID;
        k0 = blockIdx.y * 64; n0 = blockIdx.x * 32;
    } else {
        in   = w2 + (size_t)e * HID * EMB;
        outp = g_w2h + (size_t)e * EMB * HID;
        K = HID; N = EMB;
        int flat = blockIdx.x * 16 + blockIdx.y;   // 0..1407 = 44*32
        k0 = (flat % 44) * 64; n0 = (flat / 44) * 32;
    }
    int tx = threadIdx.x, ty = threadIdx.y;
#pragma unroll
    for (int i = 0; i < 8; i++)
        t[ty + 8 * i][tx] = in[(size_t)(k0 + ty + 8 * i) * N + n0 + tx];
    __syncthreads();
#pragma unroll
    for (int i = 0; i < 4; i++) {
        int n = ty + 8 * i;
        __half2 v = __floats2half2_rn(t[2 * tx][n], t[2 * tx + 1][n]);
        *(__half2*)(outp + (size_t)(n0 + n) * K + k0 + 2 * tx) = v;
    }
}

// ===================== router =====================
__global__ void k_router(const float* __restrict__ x, const float* __restrict__ wr) {
    int t    = blockIdx.x * (blockDim.x >> 5) + (threadIdx.x >> 5);
    int lane = threadIdx.x & 31;
    if (t >= NTOK) return;
    const float* xr = x + (size_t)t * EMB;
    float acc[NE];
#pragma unroll
    for (int e = 0; e < NE; e++) acc[e] = 0.f;
    for (int i = lane; i < EMB; i += 32) {
        float xv = xr[i];
#pragma unroll
        for (int e = 0; e < NE; e++) acc[e] += xv * wr[i * NE + e];
    }
#pragma unroll
    for (int e = 0; e < NE; e++)
#pragma unroll
        for (int o = 16; o > 0; o >>= 1) acc[e] += __shfl_xor_sync(0xffffffffu, acc[e], o);
    if (lane == 0) {
        int i0 = 0; float v0 = acc[0];
#pragma unroll
        for (int e = 1; e < NE; e++) if (acc[e] > v0) { v0 = acc[e]; i0 = e; }
        int i1 = -1; float v1 = -3.4e38f;
#pragma unroll
        for (int e = 0; e < NE; e++) if (e != i0 && acc[e] > v1) { v1 = acc[e]; i1 = e; }
        float z  = expf(v1 - v0);
        float p0 = 1.f / (1.f + z);
        float p1 = z  / (1.f + z);
        int s0 = atomicAdd(&g_cnt[i0], 1);
        g_tok[i0][s0] = t; g_gate[i0][s0] = p0;
        int s1 = atomicAdd(&g_cnt[i1], 1);
        g_tok[i1][s1] = t; g_gate[i1][s1] = p1;
    }
}

// ===================== gather -> fp16 ====================
__global__ void k_gather(const float* __restrict__ x) {
    int e = blockIdx.y; int cnt = g_cnt[e];
    int m0 = blockIdx.x * 16;
    int padded = (cnt + 127) & ~127;
    if (m0 >= padded) return;
    __half* dst = g_xp + (size_t)(offp_of(e) + m0) * EMB;
    for (int idx = threadIdx.x; idx < 16 * 128; idx += 256) {
        int r = idx >> 7, j = idx & 127;
        int gm = m0 + r;
        uint4 o = make_uint4(0, 0, 0, 0);
        if (gm < cnt) {
            const float4* src = (const float4*)(x + (size_t)g_tok[e][gm] * EMB) + j * 2;
            float4 v0 = src[0], v1 = src[1];
            __half2 h0 = __floats2half2_rn(v0.x, v0.y);
            __half2 h1 = __floats2half2_rn(v0.z, v0.w);
            __half2 h2 = __floats2half2_rn(v1.x, v1.y);
            __half2 h3 = __floats2half2_rn(v1.z, v1.w);
            o = make_uint4(*(uint32_t*)&h0, *(uint32_t*)&h1,
                           *(uint32_t*)&h2, *(uint32_t*)&h3);
        }
        ((uint4*)(dst + (size_t)r * EMB))[j] = o;
    }
}

// ===================== GEMM1: H = silu(X@W1)*(X@W3) =====================
// CTA tile 128(M)x64(N)x64(K), 8 warps (4x2), warp tile 32x32, 2 CTAs/SM
#define AK    72
#define A_T_H (128 * AK)
#define B_T_H (64 * AK)
#define ST1H  (A_T_H + 2 * B_T_H)
#define STG1  3
#define KB1   (EMB / 64)            // 16

__global__ void __launch_bounds__(256, 2) k_mma1() {
    extern __shared__ __half smh[];
    int e = blockIdx.z;
    int cnt = g_cnt[e];
    int m0 = blockIdx.y * 128;
    if (m0 >= cnt) return;
    int n0 = blockIdx.x * 64;
    int tid = threadIdx.x, lane = tid & 31, wid = tid >> 5;
    int wm = wid >> 1, wn = wid & 1;
    int grp = lane >> 2, q = lane & 3;
    uint32_t sbase = s2u(smh);
    int ho = offp_of(e) + m0;

    uint32_t aoff[2], boff[2];
#pragma unroll
    for (int i = 0; i < 2; i++)
        aoff[i] = (uint32_t)(((wm * 32 + i * 16 + (lane & 15)) * AK + 8 * (lane >> 4)) * 2);
#pragma unroll
    for (int jp = 0; jp < 2; jp++)
        boff[jp] = (uint32_t)(((wn * 32 + jp * 16 + (lane & 7) + 8 * (lane >> 4)) * AK
                               + 8 * ((lane >> 3) & 1)) * 2);

    const __half* gA  = g_xp  + (size_t)ho * EMB;
    const __half* gB1 = g_w1h + ((size_t)e * HID + n0) * EMB;
    const __half* gB3 = g_w3h + ((size_t)e * HID + n0) * EMB;

    auto load_stage = [&](int kb, int s) {
        uint32_t st = sbase + (uint32_t)s * ST1H * 2;
        int k0 = kb * 64;
#pragma unroll
        for (int it = 0; it < 4; it++) {
            int id = it * 256 + tid;
            int r = id >> 3, c = id & 7;
            cp16(st + (uint32_t)(r * AK) * 2 + c * 16, gA + (size_t)r * EMB + k0 + c * 8);
        }
#pragma unroll
        for (int it = 0; it < 2; it++) {
            int id = it * 256 + tid;
            int r = id >> 3, c = id & 7;
            uint32_t so = (uint32_t)(r * AK) * 2 + c * 16;
            const size_t go = (size_t)r * EMB + k0 + c * 8;
            cp16(st + A_T_H * 2 + so,           gB1 + go);
            cp16(st + (A_T_H + B_T_H) * 2 + so, gB3 + go);
        }
        CP_COMMIT();
    };

    float accZ[2][4][4], accG[2][4][4];
#pragma unroll
    for (int i = 0; i < 2; i++)
#pragma unroll
        for (int j = 0; j < 4; j++)
#pragma unroll
            for (int r = 0; r < 4; r++) { accZ[i][j][r] = 0.f; accG[i][j][r] = 0.f; }

#pragma unroll
    for (int p = 0; p < STG1 - 1; p++) load_stage(p, p);

#pragma unroll
    for (int kb = 0; kb < KB1; kb++) {
        asm volatile("cp.async.wait_group %0;" :: "n"(STG1 - 2) : "memory");
        __syncthreads();
        uint32_t stA = sbase + (uint32_t)(kb % STG1) * ST1H * 2;
        uint32_t stB1 = stA + A_T_H * 2;
        uint32_t stB3 = stA + (A_T_H + B_T_H) * 2;
#pragma unroll
        for (int ks = 0; ks < 4; ks++) {
            uint32_t ko = ks * 32;
            uint32_t a[2][4], b1[4], b3[4];
#pragma unroll
            for (int i = 0; i < 2; i++) ldsm4(a[i], stA + aoff[i] + ko);
            ldsm4(b1, stB1 + boff[0] + ko);
            ldsm4(b3, stB3 + boff[0] + ko);
#pragma unroll
            for (int i = 0; i < 2; i++) {
                mma16(accZ[i][0], a[i], b1);
                mma16(accZ[i][1], a[i], b1 + 2);
                mma16(accG[i][0], a[i], b3);
                mma16(accG[i][1], a[i], b3 + 2);
            }
            ldsm4(b1, stB1 + boff[1] + ko);
            ldsm4(b3, stB3 + boff[1] + ko);
#pragma unroll
            for (int i = 0; i < 2; i++) {
                mma16(accZ[i][2], a[i], b1);
                mma16(accZ[i][3], a[i], b1 + 2);
                mma16(accG[i][2], a[i], b3);
                mma16(accG[i][3], a[i], b3 + 2);
            }
        }
        if (kb + STG1 - 1 < KB1) load_stage(kb + STG1 - 1, (kb + STG1 - 1) % STG1);
        else CP_COMMIT();
    }

    __half* gH = g_h + (size_t)ho * HID + n0;
#pragma unroll
    for (int i = 0; i < 2; i++) {
        int r = wm * 32 + i * 16 + grp;
#pragma unroll
        for (int j = 0; j < 4; j++) {
            int c = wn * 32 + j * 8 + 2 * q;
            float h[4];
#pragma unroll
            for (int t2 = 0; t2 < 4; t2++) {
                float z = accZ[i][j][t2];
                float g = accG[i][j][t2];
                h[t2] = (z / (1.f + __expf(-z))) * g;
            }
            __half2 lo = __floats2half2_rn(h[0], h[1]);
            __half2 hi = __floats2half2_rn(h[2], h[3]);
            *(uint32_t*)(gH + (size_t)r * HID + c)       = *(uint32_t*)&lo;
            *(uint32_t*)(gH + (size_t)(r + 8) * HID + c) = *(uint32_t*)&hi;
        }
    }
}

// ===================== GEMM2: out += gate * (H @ W2) =====================
// CTA tile 128(M)x128(N)x64(K), 8 warps (4x2), warp tile 32x64, 2 CTAs/SM
#define B2_T_H (128 * AK)               // 9216 halves
#define ST2H  (A_T_H + B2_T_H)          // 18432 halves = 36864 B
#define STG2  3
#define KB2   (HID / 64)                // 44

__global__ void __launch_bounds__(256, 2) k_mma2(float* __restrict__ out) {
    extern __shared__ __half smh[];
    int e = blockIdx.z;
    int cnt = g_cnt[e];
    int m0 = blockIdx.y * 128;
    if (m0 >= cnt) return;
    int n0 = blockIdx.x * 128;
    int tid = threadIdx.x, lane = tid & 31, wid = tid >> 5;
    int wm = wid >> 1, wn = wid & 1;      // 4 x 2: warp tile 32(M) x 64(N)
    int grp = lane >> 2, q = lane & 3;
    uint32_t sbase = s2u(smh);
    int ho = offp_of(e) + m0;

    uint32_t aoff[2], boff[4];
#pragma unroll
    for (int i = 0; i < 2; i++)
        aoff[i] = (uint32_t)(((wm * 32 + i * 16 + (lane & 15)) * AK + 8 * (lane >> 4)) * 2);
#pragma unroll
    for (int jp = 0; jp < 4; jp++)
        boff[jp] = (uint32_t)(((wn * 64 + jp * 16 + (lane & 7) + 8 * (lane >> 4)) * AK
                               + 8 * ((lane >> 3) & 1)) * 2);

    const __half* gA = g_h   + (size_t)ho * HID;
    const __half* gB = g_w2h + ((size_t)e * EMB + n0) * HID;

    auto load_stage = [&](int kb, int s) {
        uint32_t st = sbase + (uint32_t)s * ST2H * 2;
        int k0 = kb * 64;
#pragma unroll
        for (int it = 0; it < 4; it++) {
            int id = it * 256 + tid;
            int r = id >> 3, c = id & 7;
            uint32_t so = (uint32_t)(r * AK) * 2 + c * 16;
            cp16(st + so,              gA + (size_t)r * HID + k0 + c * 8);
            cp16(st + A_T_H * 2 + so,  gB + (size_t)r * HID + k0 + c * 8);
        }
        CP_COMMIT();
    };

    float acc[2][8][4];
#pragma unroll
    for (int i = 0; i < 2; i++)
#pragma unroll
        for (int j = 0; j < 8; j++)
#pragma unroll
            for (int r = 0; r < 4; r++) acc[i][j][r] = 0.f;

#pragma unroll
    for (int p = 0; p < STG2 - 1; p++) load_stage(p, p);

    for (int kb = 0; kb < KB2; kb++) {
        asm volatile("cp.async.wait_group %0;" :: "n"(STG2 - 2) : "memory");
        __syncthreads();
        uint32_t stA = sbase + (uint32_t)(kb % STG2) * ST2H * 2;
        uint32_t stB = stA + A_T_H * 2;
#pragma unroll
        for (int ks = 0; ks < 4; ks++) {
            uint32_t ko = ks * 32;
            uint32_t a[2][4], b[4];
#pragma unroll
            for (int i = 0; i < 2; i++) ldsm4(a[i], stA + aoff[i] + ko);
#pragma unroll
            for (int jp = 0; jp < 4; jp++) {
                ldsm4(b, stB + boff[jp] + ko);
#pragma unroll
                for (int i = 0; i < 2; i++) {
                    mma16(acc[i][jp * 2],     a[i], b);
                    mma16(acc[i][jp * 2 + 1], a[i], b + 2);
                }
            }
        }
        if (kb + STG2 - 1 < KB2)
            load_stage(kb + STG2 - 1, (kb + STG2 - 1) % STG2);
        else CP_COMMIT();
    }

#pragma unroll
    for (int i = 0; i < 2; i++) {
        int r = wm * 32 + i * 16 + grp;
        int row0 = m0 + r, row1 = row0 + 8;
        bool act0 = row0 < cnt, act1 = row1 < cnt;
        int   t0 = act0 ? g_tok[e][row0] : 0;
        int   t1 = act1 ? g_tok[e][row1] : 0;
        float gt0 = act0 ? g_gate[e][row0] : 0.f;
        float gt1 = act1 ? g_gate[e][row1] : 0.f;
        float* o0 = out + (size_t)t0 * EMB + n0;
        float* o1 = out + (size_t)t1 * EMB + n0;
#pragma unroll
        for (int j = 0; j < 8; j++) {
            int c = wn * 64 + j * 8 + 2 * q;
            if (act0) {
                atomicAdd(&o0[c],     gt0 * acc[i][j][0]);
                atomicAdd(&o0[c + 1], gt0 * acc[i][j][1]);
            }
            if (act1) {
                atomicAdd(&o1[c],     gt1 * acc[i][j][2]);
                atomicAdd(&o1[c + 1], gt1 * acc[i][j][3]);
            }
        }
    }
}

// ===================== launcher =====================
extern "C" void kernel_launch(void* const* d_in, const int* in_sizes, int n_in,
                              void* d_out, int out_size) {
    const float* x  = (const float*)d_in[0];
    const float* wr = (const float*)d_in[1];
    const float* w1 = (const float*)d_in[2];
    const float* w3 = (const float*)d_in[3];
    const float* w2 = (const float*)d_in[4];
    float* out = (float*)d_out;

    const int SM1 = STG1 * ST1H * 2;   // 110592
    const int SM2 = STG2 * ST2H * 2;   // 110592
    cudaFuncSetAttribute(k_mma1, cudaFuncAttributeMaxDynamicSharedMemorySize, SM1);
    cudaFuncSetAttribute(k_mma2, cudaFuncAttributeMaxDynamicSharedMemorySize, SM2);

    k_roundT<<<dim3(HID / 32, EMB / 64, 3 * NE), dim3(32, 8)>>>(w1, w3, w2);
    k_router<<<NTOK / 8, 256>>>(x, wr);
    k_gather<<<dim3(NTOK / 16, NE), 256>>>(x);

    k_mma1<<<dim3(HID / 64, NTOK / 128, NE), 256, SM1>>>();

    cudaMemsetAsync(out, 0, (size_t)out_size * sizeof(float));
    k_mma2<<<dim3(EMB / 128, NTOK / 128, NE), 256, SM2>>>(out);
}